// round 2
// baseline (speedup 1.0000x reference)
#include <cuda_runtime.h>
#include <math.h>

#define LSEQ  4096
#define HID   512
#define GATES 2048
#define TTAG  24
#define NBLK  64      // CTAs per direction in recurrence
#define EDIM  300

// ---------------- scratch (static device arrays: no allocation) ----------------
__device__ float    g_x[(size_t)LSEQ * EDIM];        // embedded inputs [L,300]
__device__ float    g_preA[(size_t)LSEQ * GATES];    // fwd pre-activations [L,2048]
__device__ float    g_preB[(size_t)LSEQ * GATES];    // bwd pre-activations [L,2048]
__device__ float    g_hs0[(size_t)LSEQ * 1024];      // layer0 output (concat) [L,1024]
__device__ float    g_hs1[(size_t)LSEQ * 1024];      // layer1 output (concat) [L,1024]
__device__ float    g_emis[(size_t)LSEQ * TTAG];     // emissions [L,24]
__device__ float    g_hcur[4096];                    // h exchange: 2 phases x 2 dirs x 2 bufs x 512
__device__ unsigned g_bar[128];                      // barrier counters (stride 32)

// ---------------- embedding gather + barrier reset ----------------
__global__ void gather_kernel(const float* __restrict__ emb, const int* __restrict__ sent)
{
    if (blockIdx.x == 0 && threadIdx.x < 128) g_bar[threadIdx.x] = 0u;
    int t = blockIdx.x;
    int s = sent[t];
    const float* src = emb + (size_t)s * EDIM;
    float* dst = g_x + (size_t)t * EDIM;
    for (int e = threadIdx.x; e < EDIM; e += blockDim.x) dst[e] = src[e];
}

// ---------------- fp32 SGEMM:  C[M,N] = A[M,K] * B[N,K]^T + bias[N] ----------------
__global__ __launch_bounds__(256) void sgemm_nt(
    int M, int N, int K,
    const float* __restrict__ A, int lda,
    const float* __restrict__ B, int ldb,
    const float* __restrict__ bias,
    float* __restrict__ C, int ldc)
{
    __shared__ float As[8][128];
    __shared__ float Bs[8][128];
    const int tid = threadIdx.x;
    const int tx = tid & 15;
    const int ty = tid >> 4;
    const int m0 = blockIdx.y * 128;
    const int n0 = blockIdx.x * 128;
    const int lr = tid >> 1;         // 0..127
    const int lc = (tid & 1) * 4;    // 0 or 4

    float acc[8][8];
#pragma unroll
    for (int i2 = 0; i2 < 8; i2++)
#pragma unroll
        for (int j2 = 0; j2 < 8; j2++) acc[i2][j2] = 0.f;

    const int nkt = (K + 7) >> 3;
    for (int kt = 0; kt < nkt; kt++){
        const int k0 = kt << 3;
        const int kc = k0 + lc;
        float4 av = make_float4(0.f,0.f,0.f,0.f);
        {
            int r = m0 + lr;
            if (r < M){
                if (kc + 3 < K) av = *(const float4*)(A + (size_t)r * lda + kc);
                else {
                    if (kc + 0 < K) av.x = A[(size_t)r * lda + kc + 0];
                    if (kc + 1 < K) av.y = A[(size_t)r * lda + kc + 1];
                    if (kc + 2 < K) av.z = A[(size_t)r * lda + kc + 2];
                    if (kc + 3 < K) av.w = A[(size_t)r * lda + kc + 3];
                }
            }
        }
        float4 bv = make_float4(0.f,0.f,0.f,0.f);
        {
            int r = n0 + lr;
            if (r < N){
                if (kc + 3 < K) bv = *(const float4*)(B + (size_t)r * ldb + kc);
                else {
                    if (kc + 0 < K) bv.x = B[(size_t)r * ldb + kc + 0];
                    if (kc + 1 < K) bv.y = B[(size_t)r * ldb + kc + 1];
                    if (kc + 2 < K) bv.z = B[(size_t)r * ldb + kc + 2];
                    if (kc + 3 < K) bv.w = B[(size_t)r * ldb + kc + 3];
                }
            }
        }
        As[lc + 0][lr] = av.x; As[lc + 1][lr] = av.y; As[lc + 2][lr] = av.z; As[lc + 3][lr] = av.w;
        Bs[lc + 0][lr] = bv.x; Bs[lc + 1][lr] = bv.y; Bs[lc + 2][lr] = bv.z; Bs[lc + 3][lr] = bv.w;
        __syncthreads();
#pragma unroll
        for (int k = 0; k < 8; k++){
            float a[8], b[8];
            *(float4*)&a[0] = *(const float4*)&As[k][ty * 8];
            *(float4*)&a[4] = *(const float4*)&As[k][ty * 8 + 4];
            *(float4*)&b[0] = *(const float4*)&Bs[k][tx * 8];
            *(float4*)&b[4] = *(const float4*)&Bs[k][tx * 8 + 4];
#pragma unroll
            for (int i2 = 0; i2 < 8; i2++)
#pragma unroll
                for (int j2 = 0; j2 < 8; j2++)
                    acc[i2][j2] = fmaf(a[i2], b[j2], acc[i2][j2]);
        }
        __syncthreads();
    }
#pragma unroll
    for (int i2 = 0; i2 < 8; i2++){
        int m = m0 + ty * 8 + i2;
        if (m < M){
#pragma unroll
            for (int j2 = 0; j2 < 8; j2++){
                int n = n0 + tx * 8 + j2;
                if (n < N) C[(size_t)m * ldc + n] = acc[i2][j2] + bias[n];
            }
        }
    }
}

// ---------------- bidirectional LSTM recurrence (one layer, both directions) ----------------
// grid = 2*NBLK CTAs, 256 threads. CTA `blk` of direction `dir` owns h indices
// [blk*8, blk*8+8): 32 gate rows, each split over 8 threads (64 weight regs each).
// Per-step cross-CTA sync: monotonic counter, red.release + ld.acquire on L2.
// h exchange double-buffered in global (g_hcur), reloaded with __ldcg (L1 not coherent).
__global__ __launch_bounds__(256, 1) void lstm_rec(
    const float* __restrict__ preF, const float* __restrict__ preB,
    const float* __restrict__ whhF, const float* __restrict__ whhB,
    float* __restrict__ hsOut,      // [L,1024], fwd -> cols 0..511, bwd -> 512..1023
    float* __restrict__ hcur,       // [2 dirs][2 bufs][512]
    unsigned* __restrict__ bar)     // counters at +0 (fwd) and +32 (bwd)
{
    const int dir = blockIdx.x >> 6;
    const int blk = blockIdx.x & 63;
    const float* pre = dir ? preB : preF;
    const float* whh = dir ? whhB : whhF;
    float* hc = hcur + dir * 1024;
    unsigned* bp = bar + dir * 32;

    const int tid  = threadIdx.x;
    const int row  = tid >> 3;          // 0..31 local gate row
    const int cs   = tid & 7;           // 0..7 column slice
    const int gate = row >> 3;          // 0..3 (i,f,g,o)
    const int ii   = row & 7;           // 0..7 h index within CTA
    const int grow = gate * HID + blk * 8 + ii;   // global gate row in [0,2048)

    // register-resident weight slice: whh[grow][cs*64 .. cs*64+64)
    float w[64];
    {
        const float* wr = whh + (size_t)grow * HID + cs * 64;
#pragma unroll
        for (int k = 0; k < 64; k++) w[k] = wr[k];
    }

    __shared__ __align__(16) float sh_h[8 * 68];   // 64-blocks padded by 4 floats (bank-conflict free)
    __shared__ float sg[32];
    for (int k = tid; k < 8 * 68; k += 256) sh_h[k] = 0.f;
    float c = 0.f;                                  // cell state (threads tid<8)
    __syncthreads();

    float preCur = 0.f;
    if (cs == 0){
        int tt0 = dir ? (LSEQ - 1) : 0;
        preCur = pre[(size_t)tt0 * GATES + grow];
    }

    for (int t = 0; t < LSEQ; t++){
        const int tt = dir ? (LSEQ - 1 - t) : t;
        // prefetch next step's pre-activation (overlaps with the dot product)
        float preNext = 0.f;
        if (cs == 0 && t + 1 < LSEQ){
            int ttn = dir ? (LSEQ - 2 - t) : (t + 1);
            preNext = pre[(size_t)ttn * GATES + grow];
        }
        // 64-wide slice of the 512-dot
        float sum = 0.f;
        {
            const float4* hp = (const float4*)(sh_h + cs * 68);
#pragma unroll
            for (int k = 0; k < 16; k++){
                float4 hv = hp[k];
                sum = fmaf(w[4*k + 0], hv.x, sum);
                sum = fmaf(w[4*k + 1], hv.y, sum);
                sum = fmaf(w[4*k + 2], hv.z, sum);
                sum = fmaf(w[4*k + 3], hv.w, sum);
            }
        }
        sum += __shfl_down_sync(0xffffffffu, sum, 4);
        sum += __shfl_down_sync(0xffffffffu, sum, 2);
        sum += __shfl_down_sync(0xffffffffu, sum, 1);
        if (cs == 0) sg[row] = sum + preCur;
        __syncthreads();

        if (tid < 8){
            float zi = sg[tid], zf = sg[8 + tid], zg = sg[16 + tid], zo = sg[24 + tid];
            float ig = 1.f / (1.f + expf(-zi));
            float fg = 1.f / (1.f + expf(-zf));
            float og = 1.f / (1.f + expf(-zo));
            c = fg * c + ig * tanhf(zg);
            float h = og * tanhf(c);
            int hidx = blk * 8 + tid;
            hc[(t & 1) * HID + hidx] = h;
            hsOut[(size_t)tt * 1024 + dir * HID + hidx] = h;
        }
        __syncthreads();   // order h stores before the release

        if (tid == 0){
            asm volatile("red.release.gpu.global.add.u32 [%0], 1;" :: "l"(bp) : "memory");
            unsigned target = (unsigned)(NBLK * (t + 1));
            unsigned v;
            do {
                asm volatile("ld.acquire.gpu.global.u32 %0, [%1];" : "=r"(v) : "l"(bp) : "memory");
            } while (v < target);
        }
        __syncthreads();

        // reload full h (bypass L1: written by other SMs)
        {
            const float4* src = (const float4*)(hc + (t & 1) * HID);
            if (tid < 128) ((float4*)sh_h)[tid + (tid >> 4)] = __ldcg(src + tid);
        }
        __syncthreads();
        preCur = preNext;
    }
}

// ---------------- CRF negative log-likelihood ----------------
// block (32,24): warp j computes alpha_new[j] each step; lanes i reduce over prev tags.
__global__ void crf_kernel(const float* __restrict__ emis, const int* __restrict__ tags,
                           const float* __restrict__ startT, const float* __restrict__ endT,
                           const float* __restrict__ trans, float* __restrict__ out)
{
    const int i = threadIdx.x;   // 0..31 (prev tag lane)
    const int j = threadIdx.y;   // 0..23 (current tag)
    const int tid = j * 32 + i;
    __shared__ float alpha[TTAG];
    __shared__ float red[TTAG];

    // numerator (gold path score), parallel over t
    float acc = 0.f;
    for (int t = tid; t < LSEQ; t += 768){
        acc += emis[t * TTAG + tags[t]];
        if (t > 0) acc += trans[tags[t - 1] * TTAG + tags[t]];
    }
#pragma unroll
    for (int d = 16; d; d >>= 1) acc += __shfl_xor_sync(0xffffffffu, acc, d);
    if (i == 0) red[j] = acc;

    const float trj = (i < TTAG) ? trans[i * TTAG + j] : 0.f;
    if (i == 0) alpha[j] = startT[j] + emis[j];
    __syncthreads();

    float num = 0.f;
    if (tid == 0){
        for (int q = 0; q < TTAG; q++) num += red[q];
        num += startT[tags[0]] + endT[tags[LSEQ - 1]];
    }

    for (int t = 1; t < LSEQ; t++){
        float v = (i < TTAG) ? (alpha[i] + trj) : -3.0e38f;
        float m = v;
#pragma unroll
        for (int d = 16; d; d >>= 1) m = fmaxf(m, __shfl_xor_sync(0xffffffffu, m, d));
        float e = (i < TTAG) ? expf(v - m) : 0.f;
#pragma unroll
        for (int d = 16; d; d >>= 1) e += __shfl_xor_sync(0xffffffffu, e, d);
        float an = m + logf(e) + emis[t * TTAG + j];
        __syncthreads();
        if (i == 0) alpha[j] = an;
        __syncthreads();
    }

    if (tid == 0){
        float m = -3.0e38f;
        for (int q = 0; q < TTAG; q++) m = fmaxf(m, alpha[q] + endT[q]);
        float s = 0.f;
        for (int q = 0; q < TTAG; q++) s += expf(alpha[q] + endT[q] - m);
        out[0] = (m + logf(s)) - num;
    }
}

// ---------------- launch ----------------
extern "C" void kernel_launch(void* const* d_in, const int* in_sizes, int n_in,
                              void* d_out, int out_size)
{
    (void)in_sizes; (void)n_in; (void)out_size;
    const float* emb    = (const float*)d_in[0];
    const float* wih0f  = (const float*)d_in[1];
    const float* whh0f  = (const float*)d_in[2];
    const float* b0f    = (const float*)d_in[3];
    const float* wih0b  = (const float*)d_in[4];
    const float* whh0b  = (const float*)d_in[5];
    const float* b0b    = (const float*)d_in[6];
    const float* wih1f  = (const float*)d_in[7];
    const float* whh1f  = (const float*)d_in[8];
    const float* b1f    = (const float*)d_in[9];
    const float* wih1b  = (const float*)d_in[10];
    const float* whh1b  = (const float*)d_in[11];
    const float* b1b    = (const float*)d_in[12];
    const float* wout   = (const float*)d_in[13];
    const float* bout   = (const float*)d_in[14];
    const float* startT = (const float*)d_in[15];
    const float* endT   = (const float*)d_in[16];
    const float* trans  = (const float*)d_in[17];
    const int*   sent   = (const int*)d_in[18];
    const int*   tags   = (const int*)d_in[19];

    float *x, *preA, *preB, *hs0, *hs1, *emis, *hcur;
    unsigned* bar;
    cudaGetSymbolAddress((void**)&x,    g_x);
    cudaGetSymbolAddress((void**)&preA, g_preA);
    cudaGetSymbolAddress((void**)&preB, g_preB);
    cudaGetSymbolAddress((void**)&hs0,  g_hs0);
    cudaGetSymbolAddress((void**)&hs1,  g_hs1);
    cudaGetSymbolAddress((void**)&emis, g_emis);
    cudaGetSymbolAddress((void**)&hcur, g_hcur);
    cudaGetSymbolAddress((void**)&bar,  g_bar);

    // embedding lookup + barrier reset (runs before everything each replay)
    gather_kernel<<<LSEQ, 128>>>(emb, sent);

    // layer 0: input projections, then both-direction recurrence
    sgemm_nt<<<dim3(16, 32), 256>>>(LSEQ, GATES, EDIM, x, EDIM, wih0f, EDIM, b0f, preA, GATES);
    sgemm_nt<<<dim3(16, 32), 256>>>(LSEQ, GATES, EDIM, x, EDIM, wih0b, EDIM, b0b, preB, GATES);
    lstm_rec<<<2 * NBLK, 256>>>(preA, preB, whh0f, whh0b, hs0, hcur, bar);

    // layer 1
    sgemm_nt<<<dim3(16, 32), 256>>>(LSEQ, GATES, 1024, hs0, 1024, wih1f, 1024, b1f, preA, GATES);
    sgemm_nt<<<dim3(16, 32), 256>>>(LSEQ, GATES, 1024, hs0, 1024, wih1b, 1024, b1b, preB, GATES);
    lstm_rec<<<2 * NBLK, 256>>>(preA, preB, whh1f, whh1b, hs1, hcur + 2048, bar + 64);

    // emissions + CRF
    sgemm_nt<<<dim3(1, 32), 256>>>(LSEQ, TTAG, 1024, hs1, 1024, wout, 1024, bout, emis, TTAG);
    crf_kernel<<<1, dim3(32, 24)>>>(emis, tags, startT, endT, trans, (float*)d_out);
}

// round 5
// speedup vs baseline: 1.7101x; 1.7101x over previous
#include <cuda_runtime.h>
#include <math.h>

#define LSEQ  4096
#define HID   512
#define GATES 2048
#define TTAG  24
#define NBLK  64      // CTAs per direction in recurrence
#define EDIM  300

// ---------------- scratch (static device arrays: no allocation) ----------------
__device__ __align__(16) float g_x[(size_t)LSEQ * EDIM];        // embedded inputs [L,300]
__device__ __align__(16) float g_preA[(size_t)LSEQ * GATES];    // fwd pre-activations [L,2048]
__device__ __align__(16) float g_preB[(size_t)LSEQ * GATES];    // bwd pre-activations [L,2048]
__device__ __align__(16) float g_hs0[(size_t)LSEQ * 1024];      // layer0 output (concat) [L,1024]
__device__ __align__(16) float g_hs1[(size_t)LSEQ * 1024];      // layer1 output (concat) [L,1024]
__device__ __align__(16) float g_emis[(size_t)LSEQ * TTAG];     // emissions [L,24]
// per-step h exchange: packed {tag,h} 8B words: [layer][dir][t][512]
__device__ __align__(16) unsigned long long g_hbuf[(size_t)2 * 2 * LSEQ * HID];

// ---------------- tag reset (runs first every replay) ----------------
__global__ void fill_tags()
{
    uint4 z = make_uint4(0u, 0u, 0u, 0u);
    size_t n16 = ((size_t)2 * 2 * LSEQ * HID * 8) >> 4;   // 16B chunks
    uint4* p = (uint4*)g_hbuf;
    for (size_t i = (size_t)blockIdx.x * blockDim.x + threadIdx.x; i < n16;
         i += (size_t)gridDim.x * blockDim.x)
        p[i] = z;
}

// ---------------- embedding gather ----------------
__global__ void gather_kernel(const float* __restrict__ emb, const int* __restrict__ sent)
{
    int t = blockIdx.x;
    int s = sent[t];
    const float* src = emb + (size_t)s * EDIM;
    float* dst = g_x + (size_t)t * EDIM;
    for (int e = threadIdx.x; e < EDIM; e += blockDim.x) dst[e] = src[e];
}

// ---------------- fp32 SGEMM:  C[M,N] = A[M,K] * B[N,K]^T + bias[N] ----------------
__global__ __launch_bounds__(256) void sgemm_nt(
    int M, int N, int K,
    const float* __restrict__ A, int lda,
    const float* __restrict__ B, int ldb,
    const float* __restrict__ bias,
    float* __restrict__ C, int ldc)
{
    __shared__ float As[8][128];
    __shared__ float Bs[8][128];
    const int tid = threadIdx.x;
    const int tx = tid & 15;
    const int ty = tid >> 4;
    const int m0 = blockIdx.y * 128;
    const int n0 = blockIdx.x * 128;
    const int lr = tid >> 1;         // 0..127
    const int lc = (tid & 1) * 4;    // 0 or 4

    float acc[8][8];
#pragma unroll
    for (int i2 = 0; i2 < 8; i2++)
#pragma unroll
        for (int j2 = 0; j2 < 8; j2++) acc[i2][j2] = 0.f;

    const int nkt = (K + 7) >> 3;
    for (int kt = 0; kt < nkt; kt++){
        const int k0 = kt << 3;
        const int kc = k0 + lc;
        float4 av = make_float4(0.f,0.f,0.f,0.f);
        {
            int r = m0 + lr;
            if (r < M){
                if (kc + 3 < K) av = *(const float4*)(A + (size_t)r * lda + kc);
                else {
                    if (kc + 0 < K) av.x = A[(size_t)r * lda + kc + 0];
                    if (kc + 1 < K) av.y = A[(size_t)r * lda + kc + 1];
                    if (kc + 2 < K) av.z = A[(size_t)r * lda + kc + 2];
                    if (kc + 3 < K) av.w = A[(size_t)r * lda + kc + 3];
                }
            }
        }
        float4 bv = make_float4(0.f,0.f,0.f,0.f);
        {
            int r = n0 + lr;
            if (r < N){
                if (kc + 3 < K) bv = *(const float4*)(B + (size_t)r * ldb + kc);
                else {
                    if (kc + 0 < K) bv.x = B[(size_t)r * ldb + kc + 0];
                    if (kc + 1 < K) bv.y = B[(size_t)r * ldb + kc + 1];
                    if (kc + 2 < K) bv.z = B[(size_t)r * ldb + kc + 2];
                    if (kc + 3 < K) bv.w = B[(size_t)r * ldb + kc + 3];
                }
            }
        }
        As[lc + 0][lr] = av.x; As[lc + 1][lr] = av.y; As[lc + 2][lr] = av.z; As[lc + 3][lr] = av.w;
        Bs[lc + 0][lr] = bv.x; Bs[lc + 1][lr] = bv.y; Bs[lc + 2][lr] = bv.z; Bs[lc + 3][lr] = bv.w;
        __syncthreads();
#pragma unroll
        for (int k = 0; k < 8; k++){
            float a[8], b[8];
            *(float4*)&a[0] = *(const float4*)&As[k][ty * 8];
            *(float4*)&a[4] = *(const float4*)&As[k][ty * 8 + 4];
            *(float4*)&b[0] = *(const float4*)&Bs[k][tx * 8];
            *(float4*)&b[4] = *(const float4*)&Bs[k][tx * 8 + 4];
#pragma unroll
            for (int i2 = 0; i2 < 8; i2++)
#pragma unroll
                for (int j2 = 0; j2 < 8; j2++)
                    acc[i2][j2] = fmaf(a[i2], b[j2], acc[i2][j2]);
        }
        __syncthreads();
    }
#pragma unroll
    for (int i2 = 0; i2 < 8; i2++){
        int m = m0 + ty * 8 + i2;
        if (m < M){
#pragma unroll
            for (int j2 = 0; j2 < 8; j2++){
                int n = n0 + tx * 8 + j2;
                if (n < N) C[(size_t)m * ldc + n] = acc[i2][j2] + bias[n];
            }
        }
    }
}

// ---------------- bidirectional LSTM recurrence (one layer, both directions) ----------------
// grid = 2*NBLK CTAs, 256 threads. CTA `blk` of direction `dir` owns h indices
// [blk*8, blk*8+8): 32 gate rows, each split over 8 threads (64 weight regs each).
// Handshake: each h published as an ATOMIC 8-byte {tag=t+1, h_bits} word via st.global.cg.b64.
// Consumers poll ld.global.cg.v2.b64 until both tags EXACTLY equal t (the expected step).
// Tags are zeroed each replay; exact-match acceptance makes stale/torn data impossible.
__global__ __launch_bounds__(256, 1) void lstm_rec(
    const float* __restrict__ preF, const float* __restrict__ preB,
    const float* __restrict__ whhF, const float* __restrict__ whhB,
    float* __restrict__ hsOut,                  // [L,1024], fwd -> 0..511, bwd -> 512..1023
    unsigned long long* __restrict__ hb)        // [2 dirs][LSEQ][512] packed {tag,h}
{
    const int dir = blockIdx.x >> 6;
    const int blk = blockIdx.x & 63;
    const float* pre = dir ? preB : preF;
    const float* whh = dir ? whhB : whhF;
    unsigned long long* hbd = hb + (size_t)dir * LSEQ * HID;

    const int tid  = threadIdx.x;
    const int row  = tid >> 3;          // 0..31 local gate row
    const int cs   = tid & 7;           // 0..7 column slice
    const int gate = row >> 3;          // 0..3 (i,f,g,o)
    const int ii   = row & 7;           // 0..7 h index within CTA
    const int grow = gate * HID + blk * 8 + ii;   // global gate row in [0,2048)

    // register-resident weight slice: whh[grow][cs*64 .. cs*64+64)
    float w[64];
    {
        const float* wr = whh + (size_t)grow * HID + cs * 64;
#pragma unroll
        for (int k = 0; k < 64; k++) w[k] = wr[k];
    }

    __shared__ __align__(16) float sh_h[8 * 68];   // 64-blocks padded by 4 floats
    __shared__ float sg[32];
    for (int k = tid; k < 8 * 68; k += 256) sh_h[k] = 0.f;
    float c = 0.f;                                  // cell state (threads tid<8)
    __syncthreads();

    float preCur = 0.f;
    if (cs == 0){
        int tt0 = dir ? (LSEQ - 1) : 0;
        preCur = pre[(size_t)tt0 * GATES + grow];
    }

    for (int t = 0; t < LSEQ; t++){
        const int tt = dir ? (LSEQ - 1 - t) : t;

        // ---- acquire h(t-1): poll packed {tag,h} words; accept only on exact tag match ----
        if (t > 0){
            const unsigned long long* p = hbd + (size_t)(t - 1) * HID + 2 * tid;  // 16B aligned
            const unsigned expTag = (unsigned)t;     // step t-1 published with tag (t-1)+1 = t
            unsigned long long q0, q1;
            do {
                asm volatile("ld.global.cg.v2.b64 {%0,%1}, [%2];"
                             : "=l"(q0), "=l"(q1) : "l"(p) : "memory");
            } while ((unsigned)(q0 >> 32) != expTag || (unsigned)(q1 >> 32) != expTag);
            float2 hv = make_float2(__uint_as_float((unsigned)q0),
                                    __uint_as_float((unsigned)q1));
            *(float2*)(sh_h + 2 * tid + 4 * (tid >> 5)) = hv;   // padded layout (+4 per 64)
        }
        __syncthreads();   // sh_h ready; also orders vs previous-step sg/sh_h use

        // prefetch next step's pre-activation (overlaps with the dot product)
        float preNext = 0.f;
        if (cs == 0 && t + 1 < LSEQ){
            int ttn = dir ? (LSEQ - 2 - t) : (t + 1);
            preNext = pre[(size_t)ttn * GATES + grow];
        }

        // 64-wide slice of the 512-dot (4 accumulators to break the FMA chain)
        float s0 = 0.f, s1 = 0.f, s2 = 0.f, s3 = 0.f;
        {
            const float4* hp = (const float4*)(sh_h + cs * 68);
#pragma unroll
            for (int k = 0; k < 16; k += 4){
                float4 h0 = hp[k + 0], h1 = hp[k + 1], h2 = hp[k + 2], h3 = hp[k + 3];
                s0 = fmaf(w[4*k + 0], h0.x, s0); s0 = fmaf(w[4*k + 1], h0.y, s0);
                s0 = fmaf(w[4*k + 2], h0.z, s0); s0 = fmaf(w[4*k + 3], h0.w, s0);
                s1 = fmaf(w[4*k + 4], h1.x, s1); s1 = fmaf(w[4*k + 5], h1.y, s1);
                s1 = fmaf(w[4*k + 6], h1.z, s1); s1 = fmaf(w[4*k + 7], h1.w, s1);
                s2 = fmaf(w[4*k + 8], h2.x, s2); s2 = fmaf(w[4*k + 9], h2.y, s2);
                s2 = fmaf(w[4*k +10], h2.z, s2); s2 = fmaf(w[4*k +11], h2.w, s2);
                s3 = fmaf(w[4*k +12], h3.x, s3); s3 = fmaf(w[4*k +13], h3.y, s3);
                s3 = fmaf(w[4*k +14], h3.z, s3); s3 = fmaf(w[4*k +15], h3.w, s3);
            }
        }
        float sum = (s0 + s1) + (s2 + s3);
        sum += __shfl_down_sync(0xffffffffu, sum, 4);
        sum += __shfl_down_sync(0xffffffffu, sum, 2);
        sum += __shfl_down_sync(0xffffffffu, sum, 1);
        if (cs == 0) sg[row] = sum + preCur;
        __syncthreads();   // sg ready; all sh_h reads complete

        if (tid < 8){
            float zi = sg[tid], zf = sg[8 + tid], zg = sg[16 + tid], zo = sg[24 + tid];
            float ig = 1.f / (1.f + expf(-zi));
            float fg = 1.f / (1.f + expf(-zf));
            float og = 1.f / (1.f + expf(-zo));
            c = fg * c + ig * tanhf(zg);
            float h = og * tanhf(c);
            int hidx = blk * 8 + tid;
            // atomic 8-byte publish: {tag = t+1, h bits}, straight to L2
            unsigned long long v = ((unsigned long long)(unsigned)(t + 1) << 32)
                                 | (unsigned long long)__float_as_uint(h);
            asm volatile("st.global.cg.b64 [%0], %1;"
                         :: "l"(hbd + (size_t)t * HID + hidx), "l"(v) : "memory");
            hsOut[(size_t)tt * 1024 + dir * HID + hidx] = h;    // dense output for next GEMM
        }
        preCur = preNext;
    }
}

// ---------------- CRF negative log-likelihood ----------------
__global__ void crf_kernel(const float* __restrict__ emis, const int* __restrict__ tags,
                           const float* __restrict__ startT, const float* __restrict__ endT,
                           const float* __restrict__ trans, float* __restrict__ out)
{
    const int i = threadIdx.x;   // 0..31 (prev tag lane)
    const int j = threadIdx.y;   // 0..23 (current tag)
    const int tid = j * 32 + i;
    __shared__ float alpha[TTAG];
    __shared__ float red[TTAG];

    // numerator (gold path score), parallel over t
    float acc = 0.f;
    for (int t = tid; t < LSEQ; t += 768){
        acc += emis[t * TTAG + tags[t]];
        if (t > 0) acc += trans[tags[t - 1] * TTAG + tags[t]];
    }
#pragma unroll
    for (int d = 16; d; d >>= 1) acc += __shfl_xor_sync(0xffffffffu, acc, d);
    if (i == 0) red[j] = acc;

    const float trj = (i < TTAG) ? trans[i * TTAG + j] : 0.f;
    if (i == 0) alpha[j] = startT[j] + emis[j];
    __syncthreads();

    float num = 0.f;
    if (tid == 0){
        for (int q = 0; q < TTAG; q++) num += red[q];
        num += startT[tags[0]] + endT[tags[LSEQ - 1]];
    }

    for (int t = 1; t < LSEQ; t++){
        float v = (i < TTAG) ? (alpha[i] + trj) : -3.0e38f;
        float m = v;
#pragma unroll
        for (int d = 16; d; d >>= 1) m = fmaxf(m, __shfl_xor_sync(0xffffffffu, m, d));
        float e = (i < TTAG) ? expf(v - m) : 0.f;
#pragma unroll
        for (int d = 16; d; d >>= 1) e += __shfl_xor_sync(0xffffffffu, e, d);
        float an = m + logf(e) + emis[t * TTAG + j];
        __syncthreads();
        if (i == 0) alpha[j] = an;
        __syncthreads();
    }

    if (tid == 0){
        float m = -3.0e38f;
        for (int q = 0; q < TTAG; q++) m = fmaxf(m, alpha[q] + endT[q]);
        float s = 0.f;
        for (int q = 0; q < TTAG; q++) s += expf(alpha[q] + endT[q] - m);
        out[0] = (m + logf(s)) - num;
    }
}

// ---------------- launch ----------------
extern "C" void kernel_launch(void* const* d_in, const int* in_sizes, int n_in,
                              void* d_out, int out_size)
{
    (void)in_sizes; (void)n_in; (void)out_size;
    const float* emb    = (const float*)d_in[0];
    const float* wih0f  = (const float*)d_in[1];
    const float* whh0f  = (const float*)d_in[2];
    const float* b0f    = (const float*)d_in[3];
    const float* wih0b  = (const float*)d_in[4];
    const float* whh0b  = (const float*)d_in[5];
    const float* b0b    = (const float*)d_in[6];
    const float* wih1f  = (const float*)d_in[7];
    const float* whh1f  = (const float*)d_in[8];
    const float* b1f    = (const float*)d_in[9];
    const float* wih1b  = (const float*)d_in[10];
    const float* whh1b  = (const float*)d_in[11];
    const float* b1b    = (const float*)d_in[12];
    const float* wout   = (const float*)d_in[13];
    const float* bout   = (const float*)d_in[14];
    const float* startT = (const float*)d_in[15];
    const float* endT   = (const float*)d_in[16];
    const float* trans  = (const float*)d_in[17];
    const int*   sent   = (const int*)d_in[18];
    const int*   tags   = (const int*)d_in[19];

    float *x, *preA, *preB, *hs0, *hs1, *emis;
    unsigned long long* hbuf;
    cudaGetSymbolAddress((void**)&x,    g_x);
    cudaGetSymbolAddress((void**)&preA, g_preA);
    cudaGetSymbolAddress((void**)&preB, g_preB);
    cudaGetSymbolAddress((void**)&hs0,  g_hs0);
    cudaGetSymbolAddress((void**)&hs1,  g_hs1);
    cudaGetSymbolAddress((void**)&emis, g_emis);
    cudaGetSymbolAddress((void**)&hbuf, g_hbuf);

    // reset handshake tags + embedding gather
    fill_tags<<<4096, 256>>>();
    gather_kernel<<<LSEQ, 128>>>(emb, sent);

    // layer 0: input projections, then both-direction recurrence
    sgemm_nt<<<dim3(16, 32), 256>>>(LSEQ, GATES, EDIM, x, EDIM, wih0f, EDIM, b0f, preA, GATES);
    sgemm_nt<<<dim3(16, 32), 256>>>(LSEQ, GATES, EDIM, x, EDIM, wih0b, EDIM, b0b, preB, GATES);
    lstm_rec<<<2 * NBLK, 256>>>(preA, preB, whh0f, whh0b, hs0, hbuf);

    // layer 1
    sgemm_nt<<<dim3(16, 32), 256>>>(LSEQ, GATES, 1024, hs0, 1024, wih1f, 1024, b1f, preA, GATES);
    sgemm_nt<<<dim3(16, 32), 256>>>(LSEQ, GATES, 1024, hs0, 1024, wih1b, 1024, b1b, preB, GATES);
    lstm_rec<<<2 * NBLK, 256>>>(preA, preB, whh1f, whh1b, hs1, hbuf + (size_t)2 * LSEQ * HID);

    // emissions + CRF
    sgemm_nt<<<dim3(1, 32), 256>>>(LSEQ, TTAG, 1024, hs1, 1024, wout, 1024, bout, emis, TTAG);
    crf_kernel<<<1, dim3(32, 24)>>>(emis, tags, startT, endT, trans, (float*)d_out);
}